// round 1
// baseline (speedup 1.0000x reference)
#include <cuda_runtime.h>

#define NPTS    2048
#define THREADS 128
#define EPS     1e-5f

__global__ __launch_bounds__(THREADS) void spring_kernel(
    const float* __restrict__ X, const float* __restrict__ Kp,
    const float* __restrict__ Bp, float* __restrict__ out)
{
    __shared__ float4 xs[NPTS];
    const int b = blockIdx.y;
    const float* Xb = X + (size_t)b * NPTS * 3;

    // Stage the whole batch's points into SMEM, padded to float4 so the
    // inner loop does a single conflict-free LDS.128 per pair.
    for (int p = threadIdx.x; p < NPTS; p += THREADS) {
        xs[p] = make_float4(Xb[3*p], Xb[3*p+1], Xb[3*p+2], 0.f);
    }
    __syncthreads();

    const float K = *Kp;
    const float B = *Bp;

    const int i_local = threadIdx.x >> 2;   // 32 i's per block
    const int slice   = threadIdx.x & 3;    // 4 j-slices per i
    const int i = blockIdx.x * (THREADS / 4) + i_local;

    const float4 pi = xs[i];
    float ax = 0.f, ay = 0.f, az = 0.f;

    // Strided j so lanes in a warp touch consecutive float4s (no bank conflicts).
    #pragma unroll 8
    for (int j = slice; j < NPTS; j += 4) {
        const float4 pj = xs[j];
        const float dx = pi.x - pj.x;
        const float dy = pi.y - pj.y;
        const float dz = pi.z - pj.z;
        const float sq = dx*dx + dy*dy + dz*dz;
        // sqrt(sq) via rsqrt; guard sq==0 (diagonal) against 0*inf = NaN.
        const float dist = (sq > 0.f) ? sq * rsqrtf(sq) : 0.f;
        const float f = (K * (dist - B)) * __fdividef(1.f, dist + EPS);
        ax = fmaf(f, dx, ax);
        ay = fmaf(f, dy, ay);
        az = fmaf(f, dz, az);
    }

    // Reduce the 4 j-slices (lanes 4k..4k+3 of the same warp).
    ax += __shfl_xor_sync(0xffffffffu, ax, 1);
    ay += __shfl_xor_sync(0xffffffffu, ay, 1);
    az += __shfl_xor_sync(0xffffffffu, az, 1);
    ax += __shfl_xor_sync(0xffffffffu, ax, 2);
    ay += __shfl_xor_sync(0xffffffffu, ay, 2);
    az += __shfl_xor_sync(0xffffffffu, az, 2);

    if (slice == 0) {
        float* o = out + ((size_t)b * NPTS + i) * 3;
        o[0] = pi.x + ax;
        o[1] = pi.y + ay;
        o[2] = pi.z + az;
    }
}

extern "C" void kernel_launch(void* const* d_in, const int* in_sizes, int n_in,
                              void* d_out, int out_size) {
    const float* X = (const float*)d_in[0];
    const float* K = (const float*)d_in[1];
    const float* B = (const float*)d_in[2];
    float* out = (float*)d_out;

    const int batch = in_sizes[0] / (NPTS * 3);
    dim3 grid(NPTS / (THREADS / 4), batch);
    spring_kernel<<<grid, THREADS>>>(X, K, B, out);
}

// round 2
// speedup vs baseline: 1.0875x; 1.0875x over previous
#include <cuda_runtime.h>

#define NPTS    2048
#define THREADS 128
#define SLICES  8                 // j-slices per i
#define IPB     (THREADS/SLICES)  // 16 i's per block
#define EPS     1e-5f

__global__ __launch_bounds__(THREADS) void spring_kernel(
    const float* __restrict__ X, const float* __restrict__ Kp,
    const float* __restrict__ Bp, float* __restrict__ out)
{
    __shared__ float4 xs[NPTS];
    const int b = blockIdx.y;
    const float* Xb = X + (size_t)b * NPTS * 3;

    // Stage the whole batch into SMEM as padded float4 (one LDS.128 per pair).
    for (int p = threadIdx.x; p < NPTS; p += THREADS) {
        xs[p] = make_float4(Xb[3*p], Xb[3*p+1], Xb[3*p+2], 0.f);
    }

    const float K  = *Kp;
    const float KB = K * (*Bp);
    __syncthreads();

    const int i_local = threadIdx.x / SLICES;
    const int slice   = threadIdx.x % SLICES;
    const int i = blockIdx.x * IPB + i_local;

    const float4 pi = xs[i];
    float ax = 0.f, ay = 0.f, az = 0.f;

    // Lanes of one 8-group read 8 consecutive float4s -> conflict-free /
    // broadcast LDS.128 phases.
    #pragma unroll 8
    for (int j = slice; j < NPTS; j += SLICES) {
        const float4 pj = xs[j];
        const float dx = pi.x - pj.x;
        const float dy = pi.y - pj.y;
        const float dz = pi.z - pj.z;
        const float sq = fmaf(dx, dx, fmaf(dy, dy, dz*dz));
        // diagonal-safe: sq==0 -> dist = 0 * rsqrt(1e-12) = 0 (no predicate)
        const float dist = sq * rsqrtf(fmaxf(sq, 1e-12f));
        const float f = fmaf(K, dist, -KB) * __fdividef(1.f, dist + EPS);
        ax = fmaf(f, dx, ax);
        ay = fmaf(f, dy, ay);
        az = fmaf(f, dz, az);
    }

    // Reduce the 8 j-slices (lanes 8k..8k+7 of the same warp).
    #pragma unroll
    for (int m = 1; m < SLICES; m <<= 1) {
        ax += __shfl_xor_sync(0xffffffffu, ax, m);
        ay += __shfl_xor_sync(0xffffffffu, ay, m);
        az += __shfl_xor_sync(0xffffffffu, az, m);
    }

    if (slice == 0) {
        float* o = out + ((size_t)b * NPTS + i) * 3;
        o[0] = pi.x + ax;
        o[1] = pi.y + ay;
        o[2] = pi.z + az;
    }
}

extern "C" void kernel_launch(void* const* d_in, const int* in_sizes, int n_in,
                              void* d_out, int out_size) {
    const float* X = (const float*)d_in[0];
    const float* K = (const float*)d_in[1];
    const float* B = (const float*)d_in[2];
    float* out = (float*)d_out;

    const int batch = in_sizes[0] / (NPTS * 3);
    dim3 grid(NPTS / IPB, batch);
    spring_kernel<<<grid, THREADS>>>(X, K, B, out);
}

// round 3
// speedup vs baseline: 1.1498x; 1.0573x over previous
#include <cuda_runtime.h>

#define NPTS    2048
#define THREADS 128
#define SLICES  8                 // j-slices per i
#define IPB     (THREADS/SLICES)  // 16 i's per block
#define EPS     1e-5f

__global__ __launch_bounds__(THREADS) void spring_kernel(
    const float* __restrict__ X, const float* __restrict__ Kp,
    const float* __restrict__ Bp, float* __restrict__ out)
{
    __shared__ float4 xs[NPTS];
    __shared__ float4 red[THREADS];
    const int b = blockIdx.y;
    const float* Xb = X + (size_t)b * NPTS * 3;
    const int tid = threadIdx.x;

    // Stage batch into SMEM (padded float4) + per-thread partial sum for S.
    float sx = 0.f, sy = 0.f, sz = 0.f;
    for (int p = tid; p < NPTS; p += THREADS) {
        float4 v = make_float4(Xb[3*p], Xb[3*p+1], Xb[3*p+2], 0.f);
        xs[p] = v;
        sx += v.x; sy += v.y; sz += v.z;
    }
    red[tid] = make_float4(sx, sy, sz, 0.f);
    __syncthreads();

    // Block reduction for S = sum_j x_j.
    #pragma unroll
    for (int s = THREADS / 2; s >= 32; s >>= 1) {
        if (tid < s) {
            float4 a = red[tid], c2 = red[tid + s];
            red[tid] = make_float4(a.x + c2.x, a.y + c2.y, a.z + c2.z, 0.f);
        }
        __syncthreads();
    }
    if (tid < 32) {
        float4 a = red[tid];
        float rx = a.x, ry = a.y, rz = a.z;
        #pragma unroll
        for (int m = 16; m >= 1; m >>= 1) {
            rx += __shfl_xor_sync(0xffffffffu, rx, m);
            ry += __shfl_xor_sync(0xffffffffu, ry, m);
            rz += __shfl_xor_sync(0xffffffffu, rz, m);
        }
        if (tid == 0) red[0] = make_float4(rx, ry, rz, 0.f);
    }
    __syncthreads();
    const float4 S = red[0];

    const float K = *Kp;
    const float B = *Bp;
    const float c = K * (B + EPS);   // f = K - c * w,  w = 1/(dist+eps)

    const int i_local = tid / SLICES;
    const int slice   = tid % SLICES;
    const int i = blockIdx.x * IPB + i_local;

    const float4 pi = xs[i];
    float hx = 0.f, hy = 0.f, hz = 0.f;   // sum_j w * delta

    // Groups of 8 lanes read 8 consecutive float4s; the 4 groups in a warp
    // broadcast the same addresses -> 1-phase LDS.128.
    #pragma unroll 8
    for (int j = slice; j < NPTS; j += SLICES) {
        const float4 pj = xs[j];
        const float dx = pi.x - pj.x;
        const float dy = pi.y - pj.y;
        const float dz = pi.z - pj.z;
        const float sq = fmaf(dx, dx, fmaf(dy, dy, dz * dz));
        const float r  = rsqrtf(fmaxf(sq, 1e-12f));
        // w = 1/(sqrt(sq)+eps) = r/(1+eps*r) ~= r*(1-eps*r); err eps^2*r^2 << 1e-3.
        const float w  = r * fmaf(-EPS, r, 1.f);
        hx = fmaf(w, dx, hx);
        hy = fmaf(w, dy, hy);
        hz = fmaf(w, dz, hz);
    }

    // Reduce the 8 j-slices (lanes 8k..8k+7 of the same warp).
    #pragma unroll
    for (int m = 1; m < SLICES; m <<= 1) {
        hx += __shfl_xor_sync(0xffffffffu, hx, m);
        hy += __shfl_xor_sync(0xffffffffu, hy, m);
        hz += __shfl_xor_sync(0xffffffffu, hz, m);
    }

    if (slice == 0) {
        // out = x_i + K*(N*x_i - S) - c*h
        float* o = out + ((size_t)b * NPTS + i) * 3;
        o[0] = fmaf(K, fmaf((float)NPTS, pi.x, -S.x), fmaf(-c, hx, pi.x));
        o[1] = fmaf(K, fmaf((float)NPTS, pi.y, -S.y), fmaf(-c, hy, pi.y));
        o[2] = fmaf(K, fmaf((float)NPTS, pi.z, -S.z), fmaf(-c, hz, pi.z));
    }
}

extern "C" void kernel_launch(void* const* d_in, const int* in_sizes, int n_in,
                              void* d_out, int out_size) {
    const float* X = (const float*)d_in[0];
    const float* K = (const float*)d_in[1];
    const float* B = (const float*)d_in[2];
    float* out = (float*)d_out;

    const int batch = in_sizes[0] / (NPTS * 3);
    dim3 grid(NPTS / IPB, batch);
    spring_kernel<<<grid, THREADS>>>(X, K, B, out);
}

// round 4
// speedup vs baseline: 1.3050x; 1.1350x over previous
#include <cuda_runtime.h>

#define NPTS    2048
#define THREADS 128
#define SLICES  16
#define GRPS    (THREADS/SLICES)   // 8 thread-groups per CTA
#define IPB     (GRPS*2)           // 16 i's per CTA (2 per thread)
#define EPS     1e-5f

typedef unsigned long long ull;

__device__ __forceinline__ ull pack2(float x, float y) {
    ull v; asm("mov.b64 %0, {%1,%2};" : "=l"(v) : "f"(x), "f"(y)); return v;
}
__device__ __forceinline__ float2 unpack2(ull v) {
    float2 r; asm("mov.b64 {%0,%1}, %2;" : "=f"(r.x), "=f"(r.y) : "l"(v)); return r;
}
__device__ __forceinline__ ull fma2(ull a, ull b, ull c) {
    ull d; asm("fma.rn.f32x2 %0, %1, %2, %3;" : "=l"(d) : "l"(a), "l"(b), "l"(c)); return d;
}
__device__ __forceinline__ ull mul2(ull a, ull b) {
    ull d; asm("mul.rn.f32x2 %0, %1, %2;" : "=l"(d) : "l"(a), "l"(b)); return d;
}

__global__ __launch_bounds__(THREADS) void spring_kernel(
    const float* __restrict__ X, const float* __restrict__ Kp,
    const float* __restrict__ Bp, float* __restrict__ out)
{
    __shared__ float4 xs[NPTS];
    __shared__ float4 red[THREADS];
    const int b   = blockIdx.y;
    const int tid = threadIdx.x;
    const float* Xb = X + (size_t)b * NPTS * 3;

    // Stage batch into SMEM (padded float4) + partial sums for S = sum_j x_j.
    float sx = 0.f, sy = 0.f, sz = 0.f;
    for (int p = tid; p < NPTS; p += THREADS) {
        float4 v = make_float4(Xb[3*p], Xb[3*p+1], Xb[3*p+2], 0.f);
        xs[p] = v;
        sx += v.x; sy += v.y; sz += v.z;
    }
    red[tid] = make_float4(sx, sy, sz, 0.f);
    __syncthreads();

    #pragma unroll
    for (int s = THREADS / 2; s >= 32; s >>= 1) {
        if (tid < s) {
            float4 a = red[tid], c2 = red[tid + s];
            red[tid] = make_float4(a.x + c2.x, a.y + c2.y, a.z + c2.z, 0.f);
        }
        __syncthreads();
    }
    if (tid < 32) {
        float4 a = red[tid];
        float rx = a.x, ry = a.y, rz = a.z;
        #pragma unroll
        for (int m = 16; m >= 1; m >>= 1) {
            rx += __shfl_xor_sync(0xffffffffu, rx, m);
            ry += __shfl_xor_sync(0xffffffffu, ry, m);
            rz += __shfl_xor_sync(0xffffffffu, rz, m);
        }
        if (tid == 0) red[0] = make_float4(rx, ry, rz, 0.f);
    }
    __syncthreads();
    const float4 S = red[0];

    const float K = *Kp;
    const float c = K * (*Bp + EPS);   // f = K - c*w,  w = 1/(dist+eps)

    const int grp   = tid / SLICES;    // 0..7
    const int slice = tid % SLICES;
    const int i0 = blockIdx.x * IPB + grp;
    const int i1 = i0 + GRPS;

    const float4 p0 = xs[i0];
    const float4 p1 = xs[i1];
    const ull p0xy  = pack2(p0.x, p0.y);
    const ull p1xy  = pack2(p1.x, p1.y);
    const ull neg1  = pack2(-1.f, -1.f);

    ull   h0xy = pack2(0.f, 0.f), h1xy = pack2(0.f, 0.f);
    float h0z  = 0.f,             h1z  = 0.f;

    // 16-lane groups read 16 consecutive float4s; both warp halves broadcast
    // the same addresses. One LDS.128 feeds 2 i's.
    #pragma unroll 4
    for (int j = slice; j < NPTS; j += SLICES) {
        const float4 pj  = xs[j];
        const ull  pjxy  = pack2(pj.x, pj.y);

        // pair (i0, j)
        {
            const ull   d  = fma2(pjxy, neg1, p0xy);   // pi - pj (exact)
            const float dz = p0.z - pj.z;
            const float2 t = unpack2(mul2(d, d));      // dx^2, dy^2
            const float sq = fmaf(dz, dz, t.x) + t.y;
            const float r  = rsqrtf(fmaxf(sq, 1e-12f));
            const float w  = r * fmaf(-EPS, r, 1.f);   // ~= 1/(dist+eps)
            h0xy = fma2(pack2(w, w), d, h0xy);
            h0z  = fmaf(w, dz, h0z);
        }
        // pair (i1, j)
        {
            const ull   d  = fma2(pjxy, neg1, p1xy);
            const float dz = p1.z - pj.z;
            const float2 t = unpack2(mul2(d, d));
            const float sq = fmaf(dz, dz, t.x) + t.y;
            const float r  = rsqrtf(fmaxf(sq, 1e-12f));
            const float w  = r * fmaf(-EPS, r, 1.f);
            h1xy = fma2(pack2(w, w), d, h1xy);
            h1z  = fmaf(w, dz, h1z);
        }
    }

    float2 h0 = unpack2(h0xy);
    float2 h1 = unpack2(h1xy);
    float v0 = h0.x, v1 = h0.y, v2 = h0z, v3 = h1.x, v4 = h1.y, v5 = h1z;

    // Reduce the 16 j-slices (stays within each 16-lane half-warp group).
    #pragma unroll
    for (int m = 1; m < SLICES; m <<= 1) {
        v0 += __shfl_xor_sync(0xffffffffu, v0, m);
        v1 += __shfl_xor_sync(0xffffffffu, v1, m);
        v2 += __shfl_xor_sync(0xffffffffu, v2, m);
        v3 += __shfl_xor_sync(0xffffffffu, v3, m);
        v4 += __shfl_xor_sync(0xffffffffu, v4, m);
        v5 += __shfl_xor_sync(0xffffffffu, v5, m);
    }

    if (slice == 0) {
        // out = x_i + K*(N*x_i - S) - c*h
        float* o0 = out + ((size_t)b * NPTS + i0) * 3;
        o0[0] = fmaf(K, fmaf((float)NPTS, p0.x, -S.x), fmaf(-c, v0, p0.x));
        o0[1] = fmaf(K, fmaf((float)NPTS, p0.y, -S.y), fmaf(-c, v1, p0.y));
        o0[2] = fmaf(K, fmaf((float)NPTS, p0.z, -S.z), fmaf(-c, v2, p0.z));
        float* o1 = out + ((size_t)b * NPTS + i1) * 3;
        o1[0] = fmaf(K, fmaf((float)NPTS, p1.x, -S.x), fmaf(-c, v3, p1.x));
        o1[1] = fmaf(K, fmaf((float)NPTS, p1.y, -S.y), fmaf(-c, v4, p1.y));
        o1[2] = fmaf(K, fmaf((float)NPTS, p1.z, -S.z), fmaf(-c, v5, p1.z));
    }
}

extern "C" void kernel_launch(void* const* d_in, const int* in_sizes, int n_in,
                              void* d_out, int out_size) {
    const float* X = (const float*)d_in[0];
    const float* K = (const float*)d_in[1];
    const float* B = (const float*)d_in[2];
    float* out = (float*)d_out;

    const int batch = in_sizes[0] / (NPTS * 3);
    dim3 grid(NPTS / IPB, batch);
    spring_kernel<<<grid, THREADS>>>(X, K, B, out);
}

// round 5
// speedup vs baseline: 1.3523x; 1.0363x over previous
#include <cuda_runtime.h>

#define NPTS    2048
#define THREADS 256
#define SLICES  32                 // j-slices per i (full warp)
#define GRPS    (THREADS/SLICES)   // 8 thread-groups (warps) per CTA
#define IPB     (GRPS*2)           // 16 i's per CTA (2 per thread)
#define EPS     1e-5f

typedef unsigned long long ull;

__device__ __forceinline__ ull pack2(float x, float y) {
    ull v; asm("mov.b64 %0, {%1,%2};" : "=l"(v) : "f"(x), "f"(y)); return v;
}
__device__ __forceinline__ float2 unpack2(ull v) {
    float2 r; asm("mov.b64 {%0,%1}, %2;" : "=f"(r.x), "=f"(r.y) : "l"(v)); return r;
}
__device__ __forceinline__ ull fma2(ull a, ull b, ull c) {
    ull d; asm("fma.rn.f32x2 %0, %1, %2, %3;" : "=l"(d) : "l"(a), "l"(b), "l"(c)); return d;
}
__device__ __forceinline__ ull mul2(ull a, ull b) {
    ull d; asm("mul.rn.f32x2 %0, %1, %2;" : "=l"(d) : "l"(a), "l"(b)); return d;
}

__global__ __launch_bounds__(THREADS) void spring_kernel(
    const float* __restrict__ X, const float* __restrict__ Kp,
    const float* __restrict__ Bp, float* __restrict__ out)
{
    __shared__ float4 xs[NPTS];
    __shared__ float4 red[THREADS / 32];
    const int b   = blockIdx.y;
    const int tid = threadIdx.x;
    const float* Xb = X + (size_t)b * NPTS * 3;

    // Stage batch into SMEM (padded float4) + partial sums for S = sum_j x_j.
    float sx = 0.f, sy = 0.f, sz = 0.f;
    for (int p = tid; p < NPTS; p += THREADS) {
        float4 v = make_float4(Xb[3*p], Xb[3*p+1], Xb[3*p+2], 0.f);
        xs[p] = v;
        sx += v.x; sy += v.y; sz += v.z;
    }
    // warp-reduce the staging partials, then combine across warps
    #pragma unroll
    for (int m = 16; m >= 1; m >>= 1) {
        sx += __shfl_xor_sync(0xffffffffu, sx, m);
        sy += __shfl_xor_sync(0xffffffffu, sy, m);
        sz += __shfl_xor_sync(0xffffffffu, sz, m);
    }
    if ((tid & 31) == 0) red[tid >> 5] = make_float4(sx, sy, sz, 0.f);
    __syncthreads();
    float4 S = make_float4(0.f, 0.f, 0.f, 0.f);
    #pragma unroll
    for (int wdx = 0; wdx < THREADS / 32; wdx++) {
        S.x += red[wdx].x; S.y += red[wdx].y; S.z += red[wdx].z;
    }

    const float K = *Kp;
    const float c = K * (*Bp + EPS);   // f = K - c*w,  w = 1/(dist+eps)

    const int grp   = tid / SLICES;    // warp id, 0..7
    const int slice = tid % SLICES;    // lane
    const int i0 = blockIdx.x * IPB + grp;
    const int i1 = i0 + GRPS;

    const float4 p0 = xs[i0];
    const float4 p1 = xs[i1];
    const ull p0xy  = pack2(p0.x, p0.y);
    const ull p1xy  = pack2(p1.x, p1.y);
    const ull neg1  = pack2(-1.f, -1.f);

    ull   h0xy = pack2(0.f, 0.f), h1xy = pack2(0.f, 0.f);
    float h0z  = 0.f,             h1z  = 0.f;

    // Each warp's 32 lanes read 32 consecutive float4s: conflict-free LDS.128.
    // One load feeds 2 independent i-chains (ILP + half the LDS per pair).
    #pragma unroll 4
    for (int j = slice; j < NPTS; j += SLICES) {
        const float4 pj  = xs[j];
        const ull  pjxy  = pack2(pj.x, pj.y);

        // pair (i0, j)
        {
            const ull   d  = fma2(pjxy, neg1, p0xy);   // pi - pj (exact)
            const float dz = p0.z - pj.z;
            const float2 t = unpack2(mul2(d, d));      // dx^2, dy^2
            const float sq = fmaf(dz, dz, t.x) + t.y;
            const float r  = rsqrtf(fmaxf(sq, 1e-12f));
            const float w  = r * fmaf(-EPS, r, 1.f);   // ~= 1/(dist+eps)
            h0xy = fma2(pack2(w, w), d, h0xy);
            h0z  = fmaf(w, dz, h0z);
        }
        // pair (i1, j)
        {
            const ull   d  = fma2(pjxy, neg1, p1xy);
            const float dz = p1.z - pj.z;
            const float2 t = unpack2(mul2(d, d));
            const float sq = fmaf(dz, dz, t.x) + t.y;
            const float r  = rsqrtf(fmaxf(sq, 1e-12f));
            const float w  = r * fmaf(-EPS, r, 1.f);
            h1xy = fma2(pack2(w, w), d, h1xy);
            h1z  = fmaf(w, dz, h1z);
        }
    }

    float2 h0 = unpack2(h0xy);
    float2 h1 = unpack2(h1xy);
    float v0 = h0.x, v1 = h0.y, v2 = h0z, v3 = h1.x, v4 = h1.y, v5 = h1z;

    // Reduce the 32 j-slices across the warp.
    #pragma unroll
    for (int m = 1; m < SLICES; m <<= 1) {
        v0 += __shfl_xor_sync(0xffffffffu, v0, m);
        v1 += __shfl_xor_sync(0xffffffffu, v1, m);
        v2 += __shfl_xor_sync(0xffffffffu, v2, m);
        v3 += __shfl_xor_sync(0xffffffffu, v3, m);
        v4 += __shfl_xor_sync(0xffffffffu, v4, m);
        v5 += __shfl_xor_sync(0xffffffffu, v5, m);
    }

    if (slice == 0) {
        // out = x_i + K*(N*x_i - S) - c*h
        float* o0 = out + ((size_t)b * NPTS + i0) * 3;
        o0[0] = fmaf(K, fmaf((float)NPTS, p0.x, -S.x), fmaf(-c, v0, p0.x));
        o0[1] = fmaf(K, fmaf((float)NPTS, p0.y, -S.y), fmaf(-c, v1, p0.y));
        o0[2] = fmaf(K, fmaf((float)NPTS, p0.z, -S.z), fmaf(-c, v2, p0.z));
        float* o1 = out + ((size_t)b * NPTS + i1) * 3;
        o1[0] = fmaf(K, fmaf((float)NPTS, p1.x, -S.x), fmaf(-c, v3, p1.x));
        o1[1] = fmaf(K, fmaf((float)NPTS, p1.y, -S.y), fmaf(-c, v4, p1.y));
        o1[2] = fmaf(K, fmaf((float)NPTS, p1.z, -S.z), fmaf(-c, v5, p1.z));
    }
}

extern "C" void kernel_launch(void* const* d_in, const int* in_sizes, int n_in,
                              void* d_out, int out_size) {
    const float* X = (const float*)d_in[0];
    const float* K = (const float*)d_in[1];
    const float* B = (const float*)d_in[2];
    float* out = (float*)d_out;

    const int batch = in_sizes[0] / (NPTS * 3);
    dim3 grid(NPTS / IPB, batch);
    spring_kernel<<<grid, THREADS>>>(X, K, B, out);
}